// round 16
// baseline (speedup 1.0000x reference)
#include <cuda_runtime.h>
#include <cuda_bf16.h>
#include <cstdint>
#include <math.h>

// ---------------- problem constants ----------------
#define H_DIM 1024
#define DEPTH_N 5
#define VOCAB 32000
#define ROWS_F 2048

// ---------------- scratch (device globals; no runtime alloc allowed) ----------------
__device__ float g_bufA[2048 * 1024];                 // fp32 activations, even-level outputs
__device__ float g_bufB[1024 * 1024];                 // fp32 activations, odd-level outputs
__device__ float g_gl[1024 * 3072];                   // gate preactivations, left (+split partials)
__device__ float g_gr[1024 * 3072];                   // gate preactivations, right
__device__ __nv_bfloat16 g_actA[2048 * 1024];         // bf16 activations
__device__ __nv_bfloat16 g_actB[1024 * 1024];         // bf16 activations (enc + odd levels)
__device__ __nv_bfloat16 g_whl[3072 * 1024];          // bf16 Whh_l
__device__ __nv_bfloat16 g_whr[3072 * 1024];          // bf16 Whh_r
__device__ __nv_bfloat16 g_wout[VOCAB * 1024];        // bf16 W_out
__device__ __nv_bfloat16 g_logits[(size_t)ROWS_F * VOCAB];  // bf16 logits

// ---------------- PTX helpers ----------------
__device__ __forceinline__ uint32_t smem_u32(const void* p) {
    return (uint32_t)__cvta_generic_to_shared(p);
}
__device__ __forceinline__ void cp_async16(uint32_t dst, const void* src, bool pred) {
    int sz = pred ? 16 : 0;
    asm volatile("cp.async.cg.shared.global [%0], [%1], 16, %2;\n"
                 :: "r"(dst), "l"(src), "r"(sz));
}
__device__ __forceinline__ void cp_commit() {
    asm volatile("cp.async.commit_group;\n");
}
template <int N>
__device__ __forceinline__ void cp_wait() {
    asm volatile("cp.async.wait_group %0;\n" :: "n"(N));
}
__device__ __forceinline__ void ldmatrix_x4(uint32_t* r, uint32_t addr) {
    asm volatile("ldmatrix.sync.aligned.m8n8.x4.shared.b16 {%0,%1,%2,%3}, [%4];"
                 : "=r"(r[0]), "=r"(r[1]), "=r"(r[2]), "=r"(r[3]) : "r"(addr));
}
__device__ __forceinline__ void mma_bf16(float* c, const uint32_t* a, const uint32_t* b) {
    asm volatile(
        "mma.sync.aligned.m16n8k16.row.col.f32.bf16.bf16.f32 "
        "{%0,%1,%2,%3}, {%4,%5,%6,%7}, {%8,%9}, {%0,%1,%2,%3};\n"
        : "+f"(c[0]), "+f"(c[1]), "+f"(c[2]), "+f"(c[3])
        : "r"(a[0]), "r"(a[1]), "r"(a[2]), "r"(a[3]),
          "r"(b[0]), "r"(b[1]));
}

// SW128 swizzle (Swizzle<3,4,3>): 16B-chunk XOR within 8-row blocks
#define SWZ(o) ((o) ^ (((o) >> 3) & 0x70))

// ================= bf16 HMMA GEMM: C = A(MxK) * B(NxK)^T + bias[col] =================
// 128 threads (4 warps, each 64x64). 128x128 tile, BK=64.
// FOUR-stage cp.async pipeline with wait_group 2: prefetch distance ~2 chunks
// (~1000+ cycles) to cover L2/DRAM latency with only 4 warps/SM resident.
// Optional split-K (fp32 partials at C + s*M*N, bias on s==0) and bf16 output.
// blockIdx.z selects {B0,bias0,C0} or {B1,bias1,C1}.
#define TILEB 16384                  // 128 rows x 128B
#define GEMM_SMEM_DYN (8 * TILEB)    // 4 stages x (A + B) = 128 KB

__global__ __launch_bounds__(128)
void gemm_bf16_kernel(const __nv_bfloat16* __restrict__ A,
                      const __nv_bfloat16* __restrict__ B0, const __nv_bfloat16* __restrict__ B1,
                      const float* __restrict__ bias0, const float* __restrict__ bias1,
                      void* __restrict__ C0, void* __restrict__ C1,
                      int M, int N, int K, int splitS, int outBf16)
{
    const __nv_bfloat16* Bw = (blockIdx.z == 0) ? B0 : B1;
    const float* bias       = (blockIdx.z == 0) ? bias0 : bias1;
    void* Cz                = (blockIdx.z == 0) ? C0 : C1;

    const int Mtiles = gridDim.x / splitS;
    const int s      = blockIdx.x / Mtiles;
    const int mtile  = blockIdx.x % Mtiles;
    const int Ks     = K / splitS;
    const int kOff   = s * Ks;

    extern __shared__ char smem[];
    const uint32_t sbase = smem_u32(smem);

    const int tid  = threadIdx.x;
    const int lane = tid & 31;
    const int warp = tid >> 5;
    const int wm   = warp & 1;      // 2 warp-rows of 64
    const int wn   = warp >> 1;     // 2 warp-cols of 64
    const int tileM = mtile * 128;
    const int tileN = blockIdx.y * 128;

    float acc[4][8][4];
#pragma unroll
    for (int i = 0; i < 4; i++)
#pragma unroll
        for (int j = 0; j < 8; j++)
#pragma unroll
            for (int q = 0; q < 4; q++) acc[i][j][q] = 0.f;

    const int KT = Ks >> 6;         // chunks of 64 bf16

    auto issue_loads = [&](int stage, int kt) {
        uint32_t aB = sbase + stage * TILEB;
        uint32_t bB = sbase + 4 * TILEB + stage * TILEB;
        const __nv_bfloat16* Ak = A + (size_t)(kOff + kt * 64);
        const __nv_bfloat16* Bk = Bw + (size_t)(kOff + kt * 64);
#pragma unroll
        for (int i = 0; i < 8; i++) {
            int c = tid + i * 128;          // 1024 x 16B chunks per tile
            int row = c >> 3, c16 = c & 7;
            int gr = tileM + row;
            bool p = gr < M;
            const void* src = Ak + (size_t)(p ? gr : 0) * K + c16 * 8;
            cp_async16(aB + SWZ(row * 128 + c16 * 16), src, p);
        }
#pragma unroll
        for (int i = 0; i < 8; i++) {
            int c = tid + i * 128;
            int row = c >> 3, c16 = c & 7;
            const void* src = Bk + (size_t)(tileN + row) * K + c16 * 8;
            cp_async16(bB + SWZ(row * 128 + c16 * 16), src, true);
        }
        cp_commit();
    };

    const int j8 = lane >> 3;
    const int r8 = lane & 7;

    auto compute = [&](int stage) {
        const uint32_t aB = sbase + stage * TILEB;
        const uint32_t bB = sbase + 4 * TILEB + stage * TILEB;
#pragma unroll
        for (int ks = 0; ks < 4; ks++) {
            uint32_t af[4][4];
            uint32_t bf[4][4];
#pragma unroll
            for (int mt = 0; mt < 4; mt++) {
                int row = wm * 64 + mt * 16 + (j8 & 1) * 8 + r8;
                int o = row * 128 + ks * 32 + (j8 >> 1) * 16;
                ldmatrix_x4(af[mt], aB + SWZ(o));
            }
#pragma unroll
            for (int np = 0; np < 4; np++) {
                int row = wn * 64 + np * 16 + (j8 >> 1) * 8 + r8;
                int o = row * 128 + ks * 32 + (j8 & 1) * 16;
                ldmatrix_x4(bf[np], bB + SWZ(o));
            }
#pragma unroll
            for (int mt = 0; mt < 4; mt++)
#pragma unroll
                for (int nt = 0; nt < 8; nt++)
                    mma_bf16(acc[mt][nt], af[mt], &bf[nt >> 1][(nt & 1) * 2]);
        }
    };

    // 4-stage pipeline: issue 3 chunks ahead, wait keeps 2 in flight.
    issue_loads(0, 0);
    if (KT > 1) issue_loads(1, 1);
    if (KT > 2) issue_loads(2, 2);
    for (int kt = 0; kt < KT; kt++) {
        int rem = KT - kt - 1;            // chunks still pending beyond kt
        if (rem >= 2)      cp_wait<2>();
        else if (rem == 1) cp_wait<1>();
        else               cp_wait<0>();
        __syncthreads();
        if (kt + 3 < KT) issue_loads((kt + 3) & 3, kt + 3);
        compute(kt & 3);
    }

    // ------- epilogue -------
    const bool addBias = (s == 0);
    if (outBf16) {
        __nv_bfloat16* C = (__nv_bfloat16*)Cz;
#pragma unroll
        for (int mt = 0; mt < 4; mt++) {
            int r0 = tileM + wm * 64 + mt * 16 + (lane >> 2);
#pragma unroll
            for (int nt = 0; nt < 8; nt++) {
                int c0 = tileN + wn * 64 + nt * 8 + (lane & 3) * 2;
                float b0v = bias[c0];
                float b1v = bias[c0 + 1];
                if (r0 < M) {
                    *(__nv_bfloat162*)(C + (size_t)r0 * N + c0) =
                        __floats2bfloat162_rn(acc[mt][nt][0] + b0v, acc[mt][nt][1] + b1v);
                }
                if (r0 + 8 < M) {
                    *(__nv_bfloat162*)(C + (size_t)(r0 + 8) * N + c0) =
                        __floats2bfloat162_rn(acc[mt][nt][2] + b0v, acc[mt][nt][3] + b1v);
                }
            }
        }
    } else {
        float* C = (float*)Cz + (size_t)s * M * N;   // split-K partial region
#pragma unroll
        for (int mt = 0; mt < 4; mt++) {
            int r0 = tileM + wm * 64 + mt * 16 + (lane >> 2);
#pragma unroll
            for (int nt = 0; nt < 8; nt++) {
                int c0 = tileN + wn * 64 + nt * 8 + (lane & 3) * 2;
                float b0v = addBias ? bias[c0] : 0.f;
                float b1v = addBias ? bias[c0 + 1] : 0.f;
                if (r0 < M) {
                    float* p = C + (size_t)r0 * N + c0;
                    p[0] = acc[mt][nt][0] + b0v;
                    p[1] = acc[mt][nt][1] + b1v;
                }
                if (r0 + 8 < M) {
                    float* p = C + (size_t)(r0 + 8) * N + c0;
                    p[0] = acc[mt][nt][2] + b0v;
                    p[1] = acc[mt][nt][3] + b1v;
                }
            }
        }
    }
}

// ---------------- batched fp32 -> bf16 conversion (4 segments, one launch) ----------------
__global__ void f2b4_kernel(const float* __restrict__ s0, __nv_bfloat16* __restrict__ d0, int n0,
                            const float* __restrict__ s1, __nv_bfloat16* __restrict__ d1, int n1,
                            const float* __restrict__ s2, __nv_bfloat16* __restrict__ d2, int n2,
                            const float* __restrict__ s3, __nv_bfloat16* __restrict__ d3, int n3)
{
    int i = blockIdx.x * blockDim.x + threadIdx.x;
    const float* s; __nv_bfloat16* d; int j;
    if (i < n0)                { s = s0; d = d0; j = i; }
    else if (i < n0 + n1)      { s = s1; d = d1; j = i - n0; }
    else if (i < n0 + n1 + n2) { s = s2; d = d2; j = i - n0 - n1; }
    else if (i < n0 + n1 + n2 + n3) { s = s3; d = d3; j = i - n0 - n1 - n2; }
    else return;
    float4 v = ((const float4*)s)[j];
    ((__nv_bfloat162*)d)[2 * j]     = __floats2bfloat162_rn(v.x, v.y);
    ((__nv_bfloat162*)d)[2 * j + 1] = __floats2bfloat162_rn(v.z, v.w);
}

// ---------------- GRU gate elementwise + tree scatter (float4, split-K sum) ----------------
__device__ __forceinline__ float sigm(float x) { return 1.f / (1.f + expf(-x)); }

__global__ void gru_elem_kernel(const float* __restrict__ Gl, const float* __restrict__ Gr,
                                const float* __restrict__ cur,
                                const float* __restrict__ bih_l, const float* __restrict__ bih_r,
                                float* __restrict__ next, __nv_bfloat16* __restrict__ nextb,
                                int rows, int nodes, int psplit)
{
    int idx = blockIdx.x * blockDim.x + threadIdx.x;
    if (idx >= rows * (H_DIM / 4)) return;
    int row = idx >> 8;
    int c   = (idx & 255) << 2;
    size_t gbase = (size_t)row * 3 * H_DIM;
    size_t pspan = (size_t)rows * 3 * H_DIM;

    float4 h4 = *(const float4*)(cur + (size_t)row * H_DIM + c);
    float hv[4] = {h4.x, h4.y, h4.z, h4.w};

    float lv[4], rv[4];
#pragma unroll
    for (int side = 0; side < 2; side++) {
        const float* G  = side ? Gr : Gl;
        const float* bi = side ? bih_r : bih_l;
        float4 gr4 = *(const float4*)(G + gbase + c);
        float4 gz4 = *(const float4*)(G + gbase + H_DIM + c);
        float4 gn4 = *(const float4*)(G + gbase + 2 * H_DIM + c);
        for (int pp = 1; pp < psplit; pp++) {
            const float* Gp = G + (size_t)pp * pspan;
            float4 t;
            t = *(const float4*)(Gp + gbase + c);
            gr4.x += t.x; gr4.y += t.y; gr4.z += t.z; gr4.w += t.w;
            t = *(const float4*)(Gp + gbase + H_DIM + c);
            gz4.x += t.x; gz4.y += t.y; gz4.z += t.z; gz4.w += t.w;
            t = *(const float4*)(Gp + gbase + 2 * H_DIM + c);
            gn4.x += t.x; gn4.y += t.y; gn4.z += t.z; gn4.w += t.w;
        }
        float4 br4 = *(const float4*)(bi + c);
        float4 bz4 = *(const float4*)(bi + H_DIM + c);
        float4 bn4 = *(const float4*)(bi + 2 * H_DIM + c);
        float grs[4] = {gr4.x, gr4.y, gr4.z, gr4.w};
        float gzs[4] = {gz4.x, gz4.y, gz4.z, gz4.w};
        float gns[4] = {gn4.x, gn4.y, gn4.z, gn4.w};
        float brs[4] = {br4.x, br4.y, br4.z, br4.w};
        float bzs[4] = {bz4.x, bz4.y, bz4.z, bz4.w};
        float bns[4] = {bn4.x, bn4.y, bn4.z, bn4.w};
        float* out = side ? rv : lv;
#pragma unroll
        for (int q = 0; q < 4; q++) {
            float r = sigm(brs[q] + grs[q]);
            float z = sigm(bzs[q] + gzs[q]);
            float n = tanhf(bns[q] + r * gns[q]);
            out[q] = (1.f - z) * n + z * hv[q];
        }
    }

    int b = row / nodes;
    int j = row - b * nodes;
    size_t obase = ((size_t)(b * 2 * nodes + 2 * j)) * H_DIM + c;

    *(float4*)(next + obase)         = make_float4(lv[0], lv[1], lv[2], lv[3]);
    *(float4*)(next + obase + H_DIM) = make_float4(rv[0], rv[1], rv[2], rv[3]);

    uint2 lp, rp;
    ((__nv_bfloat162*)&lp)[0] = __floats2bfloat162_rn(lv[0], lv[1]);
    ((__nv_bfloat162*)&lp)[1] = __floats2bfloat162_rn(lv[2], lv[3]);
    ((__nv_bfloat162*)&rp)[0] = __floats2bfloat162_rn(rv[0], rv[1]);
    ((__nv_bfloat162*)&rp)[1] = __floats2bfloat162_rn(rv[2], rv[3]);
    *(uint2*)(nextb + obase)         = lp;
    *(uint2*)(nextb + obase + H_DIM) = rp;
}

// ---------------- row-wise log_softmax: bf16 logits in, fp32 out ----------------
__global__ __launch_bounds__(256)
void logsoftmax_bf16_kernel(const __nv_bfloat16* __restrict__ lg,
                            float* __restrict__ out, int V)
{
    const int row = blockIdx.x;
    const __nv_bfloat16* p = lg + (size_t)row * V;
    float* o = out + (size_t)row * V;
    const int nv = V >> 2;

    float m = -3.4e38f, s = 0.f;
    for (int i = threadIdx.x; i < nv; i += 256) {
        uint2 raw = ((const uint2*)p)[i];
        float2 v0 = __bfloat1622float2(*(const __nv_bfloat162*)&raw.x);
        float2 v1 = __bfloat1622float2(*(const __nv_bfloat162*)&raw.y);
        float vals[4] = {v0.x, v0.y, v1.x, v1.y};
#pragma unroll
        for (int q = 0; q < 4; q++) {
            float mn = fmaxf(m, vals[q]);
            s = s * __expf(m - mn) + __expf(vals[q] - mn);
            m = mn;
        }
    }
#pragma unroll
    for (int oo = 16; oo > 0; oo >>= 1) {
        float m2 = __shfl_xor_sync(0xffffffffu, m, oo);
        float s2 = __shfl_xor_sync(0xffffffffu, s, oo);
        float mn = fmaxf(m, m2);
        s = s * __expf(m - mn) + s2 * __expf(m2 - mn);
        m = mn;
    }
    __shared__ float sm[8], ss[8];
    int warp = threadIdx.x >> 5, lane = threadIdx.x & 31;
    if (lane == 0) { sm[warp] = m; ss[warp] = s; }
    __syncthreads();
    if (warp == 0) {
        float m2 = (lane < 8) ? sm[lane] : -3.4e38f;
        float s2 = (lane < 8) ? ss[lane] : 0.f;
#pragma unroll
        for (int oo = 4; oo > 0; oo >>= 1) {
            float m3 = __shfl_xor_sync(0xffffffffu, m2, oo);
            float s3 = __shfl_xor_sync(0xffffffffu, s2, oo);
            float mn = fmaxf(m2, m3);
            s2 = s2 * __expf(m2 - mn) + s3 * __expf(m3 - mn);
            m2 = mn;
        }
        if (lane == 0) { sm[0] = m2; ss[0] = s2; }
    }
    __syncthreads();
    float L = sm[0] + logf(ss[0]);
    for (int i = threadIdx.x; i < nv; i += 256) {
        uint2 raw = ((const uint2*)p)[i];
        float2 v0 = __bfloat1622float2(*(const __nv_bfloat162*)&raw.x);
        float2 v1 = __bfloat1622float2(*(const __nv_bfloat162*)&raw.y);
        ((float4*)o)[i] = make_float4(v0.x - L, v0.y - L, v1.x - L, v1.y - L);
    }
}

// ---------------- orchestration ----------------
extern "C" void kernel_launch(void* const* d_in, const int* in_sizes, int n_in,
                              void* d_out, int out_size)
{
    const float* enc   = (const float*)d_in[0];
    const float* Whh_l = (const float*)d_in[1];
    const float* bih_l = (const float*)d_in[2];
    const float* bhh_l = (const float*)d_in[3];
    const float* Whh_r = (const float*)d_in[4];
    const float* bih_r = (const float*)d_in[5];
    const float* bhh_r = (const float*)d_in[6];
    const float* W_out = (const float*)d_in[7];
    const float* b_out = (const float*)d_in[8];

    const int H = H_DIM;
    const int B = in_sizes[0] / H;   // 64
    const int V = in_sizes[8];       // 32000

    float *bufA, *bufB, *Gl, *Gr;
    __nv_bfloat16 *actA, *actB, *whl, *whr, *wout, *logits;
    cudaGetSymbolAddress((void**)&bufA, g_bufA);
    cudaGetSymbolAddress((void**)&bufB, g_bufB);
    cudaGetSymbolAddress((void**)&Gl, g_gl);
    cudaGetSymbolAddress((void**)&Gr, g_gr);
    cudaGetSymbolAddress((void**)&actA, g_actA);
    cudaGetSymbolAddress((void**)&actB, g_actB);
    cudaGetSymbolAddress((void**)&whl, g_whl);
    cudaGetSymbolAddress((void**)&whr, g_whr);
    cudaGetSymbolAddress((void**)&wout, g_wout);
    cudaGetSymbolAddress((void**)&logits, g_logits);

    cudaFuncSetAttribute(gemm_bf16_kernel,
                         cudaFuncAttributeMaxDynamicSharedMemorySize, GEMM_SMEM_DYN);

    // fp32 -> bf16 conversions, one launch for all 4 segments
    {
        int n0 = (3 * H * H) / 4;          // Whh_l
        int n1 = n0;                       // Whh_r
        int n2 = (V * H) / 4;              // W_out
        int n3 = (B * H) / 4;              // enc
        int tot = n0 + n1 + n2 + n3;
        f2b4_kernel<<<(tot + 255) / 256, 256>>>(Whh_l, whl, n0,
                                                Whh_r, whr, n1,
                                                W_out, wout, n2,
                                                enc, actB, n3);
    }

    const float* cur = enc;
    const __nv_bfloat16* curb = actB;
    int rows = B;
    for (int d = 0; d < DEPTH_N; d++) {
        int split = (rows <= 128) ? 2 : 1;       // fill the chip on small levels
        int mtiles = (rows + 127) / 128;
        dim3 grid(mtiles * split, (3 * H) / 128, 2);
        gemm_bf16_kernel<<<grid, 128, GEMM_SMEM_DYN>>>(
            curb, whl, whr, bhh_l, bhh_r, Gl, Gr, rows, 3 * H, H, split, 0);

        float* next = (d & 1) ? bufB : bufA;
        __nv_bfloat16* nextb = (d & 1) ? actB : actA;
        int nodes = rows / B;
        int tot4 = rows * (H / 4);
        gru_elem_kernel<<<(tot4 + 255) / 256, 256>>>(
            Gl, Gr, cur, bih_l, bih_r, next, nextb, rows, nodes, split);
        cur = next;
        curb = nextb;
        rows *= 2;
    }

    // logits (bf16) = cur @ W_out^T + b_out   (M-major grid for W_out L2 reuse)
    {
        dim3 grid(rows / 128, V / 128, 1);
        gemm_bf16_kernel<<<grid, 128, GEMM_SMEM_DYN>>>(
            curb, wout, wout, b_out, b_out, logits, logits, rows, V, H, 1, 1);
    }

    // log_softmax: bf16 logits -> fp32 d_out
    logsoftmax_bf16_kernel<<<rows, 256>>>(logits, (float*)d_out, V);
}

// round 17
// speedup vs baseline: 1.1828x; 1.1828x over previous
#include <cuda_runtime.h>
#include <cuda_bf16.h>
#include <cstdint>
#include <math.h>

// ---------------- problem constants ----------------
#define H_DIM 1024
#define DEPTH_N 5
#define VOCAB 32000
#define ROWS_F 2048

// ---------------- scratch (device globals; no runtime alloc allowed) ----------------
__device__ float g_bufA[2048 * 1024];                 // fp32 activations, even-level outputs
__device__ float g_bufB[1024 * 1024];                 // fp32 activations, odd-level outputs
__device__ float g_gl[1024 * 3072];                   // gate preactivations, left (+split partials)
__device__ float g_gr[1024 * 3072];                   // gate preactivations, right
__device__ __nv_bfloat16 g_actA[2048 * 1024];         // bf16 activations
__device__ __nv_bfloat16 g_actB[1024 * 1024];         // bf16 activations (enc + odd levels)
__device__ __nv_bfloat16 g_whl[3072 * 1024];          // bf16 Whh_l
__device__ __nv_bfloat16 g_whr[3072 * 1024];          // bf16 Whh_r
__device__ __nv_bfloat16 g_wout[VOCAB * 1024];        // bf16 W_out
__device__ __nv_bfloat16 g_logits[(size_t)ROWS_F * VOCAB];  // bf16 logits

// ---------------- PTX helpers ----------------
__device__ __forceinline__ uint32_t smem_u32(const void* p) {
    return (uint32_t)__cvta_generic_to_shared(p);
}
__device__ __forceinline__ void cp_async16(uint32_t dst, const void* src, bool pred) {
    int sz = pred ? 16 : 0;
    asm volatile("cp.async.cg.shared.global [%0], [%1], 16, %2;\n"
                 :: "r"(dst), "l"(src), "r"(sz));
}
__device__ __forceinline__ void cp_commit() {
    asm volatile("cp.async.commit_group;\n");
}
template <int N>
__device__ __forceinline__ void cp_wait() {
    asm volatile("cp.async.wait_group %0;\n" :: "n"(N));
}
__device__ __forceinline__ void ldmatrix_x4(uint32_t* r, uint32_t addr) {
    asm volatile("ldmatrix.sync.aligned.m8n8.x4.shared.b16 {%0,%1,%2,%3}, [%4];"
                 : "=r"(r[0]), "=r"(r[1]), "=r"(r[2]), "=r"(r[3]) : "r"(addr));
}
__device__ __forceinline__ void mma_bf16(float* c, const uint32_t* a, const uint32_t* b) {
    asm volatile(
        "mma.sync.aligned.m16n8k16.row.col.f32.bf16.bf16.f32 "
        "{%0,%1,%2,%3}, {%4,%5,%6,%7}, {%8,%9}, {%0,%1,%2,%3};\n"
        : "+f"(c[0]), "+f"(c[1]), "+f"(c[2]), "+f"(c[3])
        : "r"(a[0]), "r"(a[1]), "r"(a[2]), "r"(a[3]),
          "r"(b[0]), "r"(b[1]));
}

// SW128 swizzle (Swizzle<3,4,3>): 16B-chunk XOR within 8-row blocks
#define SWZ(o) ((o) ^ (((o) >> 3) & 0x70))

#define TILEB 16384                  // 128 rows x 128B
#define GEMM_SMEM_DYN (6 * TILEB)    // 3 stages x (A + B) = 96 KB

// ================= GRU GEMM: fp32 out + split-K (specialized; R13 mainloop) =================
__global__ __launch_bounds__(128)
void gemm_gru_kernel(const __nv_bfloat16* __restrict__ A,
                     const __nv_bfloat16* __restrict__ B0, const __nv_bfloat16* __restrict__ B1,
                     const float* __restrict__ bias0, const float* __restrict__ bias1,
                     float* __restrict__ C0, float* __restrict__ C1,
                     int M, int N, int K, int splitS)
{
    const __nv_bfloat16* Bw = (blockIdx.z == 0) ? B0 : B1;
    const float* bias       = (blockIdx.z == 0) ? bias0 : bias1;
    float* Cz               = (blockIdx.z == 0) ? C0 : C1;

    const int Mtiles = gridDim.x / splitS;
    const int s      = blockIdx.x / Mtiles;
    const int mtile  = blockIdx.x % Mtiles;
    const int Ks     = K / splitS;
    const int kOff   = s * Ks;

    extern __shared__ char smem[];
    const uint32_t sbase = smem_u32(smem);

    const int tid  = threadIdx.x;
    const int lane = tid & 31;
    const int warp = tid >> 5;
    const int wm   = warp & 1;
    const int wn   = warp >> 1;
    const int tileM = mtile * 128;
    const int tileN = blockIdx.y * 128;

    float acc[4][8][4];
#pragma unroll
    for (int i = 0; i < 4; i++)
#pragma unroll
        for (int j = 0; j < 8; j++)
#pragma unroll
            for (int q = 0; q < 4; q++) acc[i][j][q] = 0.f;

    const int KT = Ks >> 6;

    auto issue_loads = [&](int stage, int kt) {
        uint32_t aB = sbase + stage * TILEB;
        uint32_t bB = sbase + 3 * TILEB + stage * TILEB;
        const __nv_bfloat16* Ak = A + (size_t)(kOff + kt * 64);
        const __nv_bfloat16* Bk = Bw + (size_t)(kOff + kt * 64);
#pragma unroll
        for (int i = 0; i < 8; i++) {
            int c = tid + i * 128;
            int row = c >> 3, c16 = c & 7;
            int gr = tileM + row;
            bool p = gr < M;
            const void* src = Ak + (size_t)(p ? gr : 0) * K + c16 * 8;
            cp_async16(aB + SWZ(row * 128 + c16 * 16), src, p);
        }
#pragma unroll
        for (int i = 0; i < 8; i++) {
            int c = tid + i * 128;
            int row = c >> 3, c16 = c & 7;
            const void* src = Bk + (size_t)(tileN + row) * K + c16 * 8;
            cp_async16(bB + SWZ(row * 128 + c16 * 16), src, true);
        }
        cp_commit();
    };

    const int j8 = lane >> 3;
    const int r8 = lane & 7;

    auto compute = [&](int stage) {
        const uint32_t aB = sbase + stage * TILEB;
        const uint32_t bB = sbase + 3 * TILEB + stage * TILEB;
#pragma unroll
        for (int ks = 0; ks < 4; ks++) {
            uint32_t af[4][4];
            uint32_t bf[4][4];
#pragma unroll
            for (int mt = 0; mt < 4; mt++) {
                int row = wm * 64 + mt * 16 + (j8 & 1) * 8 + r8;
                int o = row * 128 + ks * 32 + (j8 >> 1) * 16;
                ldmatrix_x4(af[mt], aB + SWZ(o));
            }
#pragma unroll
            for (int np = 0; np < 4; np++) {
                int row = wn * 64 + np * 16 + (j8 >> 1) * 8 + r8;
                int o = row * 128 + ks * 32 + (j8 & 1) * 16;
                ldmatrix_x4(bf[np], bB + SWZ(o));
            }
#pragma unroll
            for (int mt = 0; mt < 4; mt++)
#pragma unroll
                for (int nt = 0; nt < 8; nt++)
                    mma_bf16(acc[mt][nt], af[mt], &bf[nt >> 1][(nt & 1) * 2]);
        }
    };

    issue_loads(0, 0);
    if (KT > 1) issue_loads(1, 1);
    for (int kt = 0; kt < KT; kt++) {
        if (kt == KT - 1) cp_wait<0>(); else cp_wait<1>();
        __syncthreads();
        if (kt + 2 < KT) issue_loads((kt + 2) % 3, kt + 2);
        compute(kt % 3);
    }

    const bool addBias = (s == 0);
    float* C = Cz + (size_t)s * M * N;
#pragma unroll
    for (int mt = 0; mt < 4; mt++) {
        int r0 = tileM + wm * 64 + mt * 16 + (lane >> 2);
#pragma unroll
        for (int nt = 0; nt < 8; nt++) {
            int c0 = tileN + wn * 64 + nt * 8 + (lane & 3) * 2;
            float b0v = addBias ? bias[c0] : 0.f;
            float b1v = addBias ? bias[c0 + 1] : 0.f;
            if (r0 < M) {
                float* p = C + (size_t)r0 * N + c0;
                p[0] = acc[mt][nt][0] + b0v;
                p[1] = acc[mt][nt][1] + b1v;
            }
            if (r0 + 8 < M) {
                float* p = C + (size_t)(r0 + 8) * N + c0;
                p[0] = acc[mt][nt][2] + b0v;
                p[1] = acc[mt][nt][3] + b1v;
            }
        }
    }
}

// ================= logits GEMM: bf16 out, no split (specialized; R13 mainloop) =================
__global__ __launch_bounds__(128)
void gemm_logits_kernel(const __nv_bfloat16* __restrict__ A,
                        const __nv_bfloat16* __restrict__ Bw,
                        const float* __restrict__ bias,
                        __nv_bfloat16* __restrict__ C,
                        int M, int N, int K)
{
    extern __shared__ char smem[];
    const uint32_t sbase = smem_u32(smem);

    const int tid  = threadIdx.x;
    const int lane = tid & 31;
    const int warp = tid >> 5;
    const int wm   = warp & 1;
    const int wn   = warp >> 1;
    const int tileM = blockIdx.x * 128;
    const int tileN = blockIdx.y * 128;

    float acc[4][8][4];
#pragma unroll
    for (int i = 0; i < 4; i++)
#pragma unroll
        for (int j = 0; j < 8; j++)
#pragma unroll
            for (int q = 0; q < 4; q++) acc[i][j][q] = 0.f;

    const int KT = K >> 6;     // 16

    auto issue_loads = [&](int stage, int kt) {
        uint32_t aB = sbase + stage * TILEB;
        uint32_t bB = sbase + 3 * TILEB + stage * TILEB;
        const __nv_bfloat16* Ak = A + (size_t)kt * 64;
        const __nv_bfloat16* Bk = Bw + (size_t)kt * 64;
#pragma unroll
        for (int i = 0; i < 8; i++) {
            int c = tid + i * 128;
            int row = c >> 3, c16 = c & 7;
            const void* src = Ak + (size_t)(tileM + row) * K + c16 * 8;
            cp_async16(aB + SWZ(row * 128 + c16 * 16), src, true);
        }
#pragma unroll
        for (int i = 0; i < 8; i++) {
            int c = tid + i * 128;
            int row = c >> 3, c16 = c & 7;
            const void* src = Bk + (size_t)(tileN + row) * K + c16 * 8;
            cp_async16(bB + SWZ(row * 128 + c16 * 16), src, true);
        }
        cp_commit();
    };

    const int j8 = lane >> 3;
    const int r8 = lane & 7;

    auto compute = [&](int stage) {
        const uint32_t aB = sbase + stage * TILEB;
        const uint32_t bB = sbase + 3 * TILEB + stage * TILEB;
#pragma unroll
        for (int ks = 0; ks < 4; ks++) {
            uint32_t af[4][4];
            uint32_t bf[4][4];
#pragma unroll
            for (int mt = 0; mt < 4; mt++) {
                int row = wm * 64 + mt * 16 + (j8 & 1) * 8 + r8;
                int o = row * 128 + ks * 32 + (j8 >> 1) * 16;
                ldmatrix_x4(af[mt], aB + SWZ(o));
            }
#pragma unroll
            for (int np = 0; np < 4; np++) {
                int row = wn * 64 + np * 16 + (j8 >> 1) * 8 + r8;
                int o = row * 128 + ks * 32 + (j8 & 1) * 16;
                ldmatrix_x4(bf[np], bB + SWZ(o));
            }
#pragma unroll
            for (int mt = 0; mt < 4; mt++)
#pragma unroll
                for (int nt = 0; nt < 8; nt++)
                    mma_bf16(acc[mt][nt], af[mt], &bf[nt >> 1][(nt & 1) * 2]);
        }
    };

    issue_loads(0, 0);
    issue_loads(1, 1);
    for (int kt = 0; kt < KT; kt++) {
        if (kt == KT - 1) cp_wait<0>(); else cp_wait<1>();
        __syncthreads();
        if (kt + 2 < KT) issue_loads((kt + 2) % 3, kt + 2);
        compute(kt % 3);
    }

    // bf16 epilogue with bias (M=2048, N=32000 exact multiples -> no guards)
#pragma unroll
    for (int mt = 0; mt < 4; mt++) {
        int r0 = tileM + wm * 64 + mt * 16 + (lane >> 2);
#pragma unroll
        for (int nt = 0; nt < 8; nt++) {
            int c0 = tileN + wn * 64 + nt * 8 + (lane & 3) * 2;
            float b0v = bias[c0];
            float b1v = bias[c0 + 1];
            *(__nv_bfloat162*)(C + (size_t)r0 * N + c0) =
                __floats2bfloat162_rn(acc[mt][nt][0] + b0v, acc[mt][nt][1] + b1v);
            *(__nv_bfloat162*)(C + (size_t)(r0 + 8) * N + c0) =
                __floats2bfloat162_rn(acc[mt][nt][2] + b0v, acc[mt][nt][3] + b1v);
        }
    }
}

// ---------------- batched fp32 -> bf16 conversion (4 segments, one launch) ----------------
__global__ void f2b4_kernel(const float* __restrict__ s0, __nv_bfloat16* __restrict__ d0, int n0,
                            const float* __restrict__ s1, __nv_bfloat16* __restrict__ d1, int n1,
                            const float* __restrict__ s2, __nv_bfloat16* __restrict__ d2, int n2,
                            const float* __restrict__ s3, __nv_bfloat16* __restrict__ d3, int n3)
{
    int i = blockIdx.x * blockDim.x + threadIdx.x;
    const float* s; __nv_bfloat16* d; int j;
    if (i < n0)                { s = s0; d = d0; j = i; }
    else if (i < n0 + n1)      { s = s1; d = d1; j = i - n0; }
    else if (i < n0 + n1 + n2) { s = s2; d = d2; j = i - n0 - n1; }
    else if (i < n0 + n1 + n2 + n3) { s = s3; d = d3; j = i - n0 - n1 - n2; }
    else return;
    float4 v = ((const float4*)s)[j];
    ((__nv_bfloat162*)d)[2 * j]     = __floats2bfloat162_rn(v.x, v.y);
    ((__nv_bfloat162*)d)[2 * j + 1] = __floats2bfloat162_rn(v.z, v.w);
}

// ---------------- GRU gate elementwise + tree scatter (float4, split-K sum) ----------------
__device__ __forceinline__ float sigm(float x) { return 1.f / (1.f + expf(-x)); }

__global__ void gru_elem_kernel(const float* __restrict__ Gl, const float* __restrict__ Gr,
                                const float* __restrict__ cur,
                                const float* __restrict__ bih_l, const float* __restrict__ bih_r,
                                float* __restrict__ next, __nv_bfloat16* __restrict__ nextb,
                                int rows, int nodes, int psplit)
{
    int idx = blockIdx.x * blockDim.x + threadIdx.x;
    if (idx >= rows * (H_DIM / 4)) return;
    int row = idx >> 8;
    int c   = (idx & 255) << 2;
    size_t gbase = (size_t)row * 3 * H_DIM;
    size_t pspan = (size_t)rows * 3 * H_DIM;

    float4 h4 = *(const float4*)(cur + (size_t)row * H_DIM + c);
    float hv[4] = {h4.x, h4.y, h4.z, h4.w};

    float lv[4], rv[4];
#pragma unroll
    for (int side = 0; side < 2; side++) {
        const float* G  = side ? Gr : Gl;
        const float* bi = side ? bih_r : bih_l;
        float4 gr4 = *(const float4*)(G + gbase + c);
        float4 gz4 = *(const float4*)(G + gbase + H_DIM + c);
        float4 gn4 = *(const float4*)(G + gbase + 2 * H_DIM + c);
        for (int pp = 1; pp < psplit; pp++) {
            const float* Gp = G + (size_t)pp * pspan;
            float4 t;
            t = *(const float4*)(Gp + gbase + c);
            gr4.x += t.x; gr4.y += t.y; gr4.z += t.z; gr4.w += t.w;
            t = *(const float4*)(Gp + gbase + H_DIM + c);
            gz4.x += t.x; gz4.y += t.y; gz4.z += t.z; gz4.w += t.w;
            t = *(const float4*)(Gp + gbase + 2 * H_DIM + c);
            gn4.x += t.x; gn4.y += t.y; gn4.z += t.z; gn4.w += t.w;
        }
        float4 br4 = *(const float4*)(bi + c);
        float4 bz4 = *(const float4*)(bi + H_DIM + c);
        float4 bn4 = *(const float4*)(bi + 2 * H_DIM + c);
        float grs[4] = {gr4.x, gr4.y, gr4.z, gr4.w};
        float gzs[4] = {gz4.x, gz4.y, gz4.z, gz4.w};
        float gns[4] = {gn4.x, gn4.y, gn4.z, gn4.w};
        float brs[4] = {br4.x, br4.y, br4.z, br4.w};
        float bzs[4] = {bz4.x, bz4.y, bz4.z, bz4.w};
        float bns[4] = {bn4.x, bn4.y, bn4.z, bn4.w};
        float* out = side ? rv : lv;
#pragma unroll
        for (int q = 0; q < 4; q++) {
            float r = sigm(brs[q] + grs[q]);
            float z = sigm(bzs[q] + gzs[q]);
            float n = tanhf(bns[q] + r * gns[q]);
            out[q] = (1.f - z) * n + z * hv[q];
        }
    }

    int b = row / nodes;
    int j = row - b * nodes;
    size_t obase = ((size_t)(b * 2 * nodes + 2 * j)) * H_DIM + c;

    *(float4*)(next + obase)         = make_float4(lv[0], lv[1], lv[2], lv[3]);
    *(float4*)(next + obase + H_DIM) = make_float4(rv[0], rv[1], rv[2], rv[3]);

    uint2 lp, rp;
    ((__nv_bfloat162*)&lp)[0] = __floats2bfloat162_rn(lv[0], lv[1]);
    ((__nv_bfloat162*)&lp)[1] = __floats2bfloat162_rn(lv[2], lv[3]);
    ((__nv_bfloat162*)&rp)[0] = __floats2bfloat162_rn(rv[0], rv[1]);
    ((__nv_bfloat162*)&rp)[1] = __floats2bfloat162_rn(rv[2], rv[3]);
    *(uint2*)(nextb + obase)         = lp;
    *(uint2*)(nextb + obase + H_DIM) = rp;
}

// ---------------- log_softmax: bf16 row cached in smem, ONE DRAM read ----------------
// Row = 32000 bf16 = 64000 B smem. 256 threads.
#define LSM_SMEM (VOCAB * 2)

__global__ __launch_bounds__(256)
void logsoftmax_smem_kernel(const __nv_bfloat16* __restrict__ lg,
                            float* __restrict__ out, int V)
{
    extern __shared__ uint4 srow[];          // V/8 uint4 chunks
    const int row = blockIdx.x;
    const uint4* p = (const uint4*)(lg + (size_t)row * V);
    float* o = out + (size_t)row * V;
    const int nch = V >> 3;                  // 4000 chunks of 8 bf16

    float m = -3.4e38f, s = 0.f;
    for (int i = threadIdx.x; i < nch; i += 256) {
        uint4 raw = p[i];
        srow[i] = raw;
        const __nv_bfloat162* h = (const __nv_bfloat162*)&raw;
#pragma unroll
        for (int q = 0; q < 4; q++) {
            float2 v = __bfloat1622float2(h[q]);
            float mn = fmaxf(m, fmaxf(v.x, v.y));
            s = s * __expf(m - mn) + __expf(v.x - mn) + __expf(v.y - mn);
            m = mn;
        }
    }
#pragma unroll
    for (int oo = 16; oo > 0; oo >>= 1) {
        float m2 = __shfl_xor_sync(0xffffffffu, m, oo);
        float s2 = __shfl_xor_sync(0xffffffffu, s, oo);
        float mn = fmaxf(m, m2);
        s = s * __expf(m - mn) + s2 * __expf(m2 - mn);
        m = mn;
    }
    __shared__ float sm[8], ss[8];
    int warp = threadIdx.x >> 5, lane = threadIdx.x & 31;
    if (lane == 0) { sm[warp] = m; ss[warp] = s; }
    __syncthreads();
    if (warp == 0) {
        float m2 = (lane < 8) ? sm[lane] : -3.4e38f;
        float s2 = (lane < 8) ? ss[lane] : 0.f;
#pragma unroll
        for (int oo = 4; oo > 0; oo >>= 1) {
            float m3 = __shfl_xor_sync(0xffffffffu, m2, oo);
            float s3 = __shfl_xor_sync(0xffffffffu, s2, oo);
            float mn = fmaxf(m2, m3);
            s2 = s2 * __expf(m2 - mn) + s3 * __expf(m3 - mn);
            m2 = mn;
        }
        if (lane == 0) { sm[0] = m2; ss[0] = s2; }
    }
    __syncthreads();
    float L = sm[0] + logf(ss[0]);

    // pass 2 from smem
    for (int i = threadIdx.x; i < nch; i += 256) {
        uint4 raw = srow[i];
        const __nv_bfloat162* h = (const __nv_bfloat162*)&raw;
        float2 v0 = __bfloat1622float2(h[0]);
        float2 v1 = __bfloat1622float2(h[1]);
        float2 v2 = __bfloat1622float2(h[2]);
        float2 v3 = __bfloat1622float2(h[3]);
        ((float4*)o)[2 * i]     = make_float4(v0.x - L, v0.y - L, v1.x - L, v1.y - L);
        ((float4*)o)[2 * i + 1] = make_float4(v2.x - L, v2.y - L, v3.x - L, v3.y - L);
    }
}

// ---------------- orchestration ----------------
extern "C" void kernel_launch(void* const* d_in, const int* in_sizes, int n_in,
                              void* d_out, int out_size)
{
    const float* enc   = (const float*)d_in[0];
    const float* Whh_l = (const float*)d_in[1];
    const float* bih_l = (const float*)d_in[2];
    const float* bhh_l = (const float*)d_in[3];
    const float* Whh_r = (const float*)d_in[4];
    const float* bih_r = (const float*)d_in[5];
    const float* bhh_r = (const float*)d_in[6];
    const float* W_out = (const float*)d_in[7];
    const float* b_out = (const float*)d_in[8];

    const int H = H_DIM;
    const int B = in_sizes[0] / H;   // 64
    const int V = in_sizes[8];       // 32000

    float *bufA, *bufB, *Gl, *Gr;
    __nv_bfloat16 *actA, *actB, *whl, *whr, *wout, *logits;
    cudaGetSymbolAddress((void**)&bufA, g_bufA);
    cudaGetSymbolAddress((void**)&bufB, g_bufB);
    cudaGetSymbolAddress((void**)&Gl, g_gl);
    cudaGetSymbolAddress((void**)&Gr, g_gr);
    cudaGetSymbolAddress((void**)&actA, g_actA);
    cudaGetSymbolAddress((void**)&actB, g_actB);
    cudaGetSymbolAddress((void**)&whl, g_whl);
    cudaGetSymbolAddress((void**)&whr, g_whr);
    cudaGetSymbolAddress((void**)&wout, g_wout);
    cudaGetSymbolAddress((void**)&logits, g_logits);

    cudaFuncSetAttribute(gemm_gru_kernel,
                         cudaFuncAttributeMaxDynamicSharedMemorySize, GEMM_SMEM_DYN);
    cudaFuncSetAttribute(gemm_logits_kernel,
                         cudaFuncAttributeMaxDynamicSharedMemorySize, GEMM_SMEM_DYN);
    cudaFuncSetAttribute(logsoftmax_smem_kernel,
                         cudaFuncAttributeMaxDynamicSharedMemorySize, LSM_SMEM);

    // fp32 -> bf16 conversions, one launch for all 4 segments
    {
        int n0 = (3 * H * H) / 4;          // Whh_l
        int n1 = n0;                       // Whh_r
        int n2 = (V * H) / 4;              // W_out
        int n3 = (B * H) / 4;              // enc
        int tot = n0 + n1 + n2 + n3;
        f2b4_kernel<<<(tot + 255) / 256, 256>>>(Whh_l, whl, n0,
                                                Whh_r, whr, n1,
                                                W_out, wout, n2,
                                                enc, actB, n3);
    }

    const float* cur = enc;
    const __nv_bfloat16* curb = actB;
    int rows = B;
    for (int d = 0; d < DEPTH_N; d++) {
        int split = (rows <= 128) ? 2 : 1;       // fill the chip on small levels
        int mtiles = (rows + 127) / 128;
        dim3 grid(mtiles * split, (3 * H) / 128, 2);
        gemm_gru_kernel<<<grid, 128, GEMM_SMEM_DYN>>>(
            curb, whl, whr, bhh_l, bhh_r, Gl, Gr, rows, 3 * H, H, split);

        float* next = (d & 1) ? bufB : bufA;
        __nv_bfloat16* nextb = (d & 1) ? actB : actA;
        int nodes = rows / B;
        int tot4 = rows * (H / 4);
        gru_elem_kernel<<<(tot4 + 255) / 256, 256>>>(
            Gl, Gr, cur, bih_l, bih_r, next, nextb, rows, nodes, split);
        cur = next;
        curb = nextb;
        rows *= 2;
    }

    // logits (bf16) = cur @ W_out^T + b_out   (M-major grid for W_out L2 reuse)
    {
        dim3 grid(rows / 128, V / 128, 1);
        gemm_logits_kernel<<<grid, 128, GEMM_SMEM_DYN>>>(
            curb, wout, b_out, logits, rows, V, H);
    }

    // log_softmax: one DRAM read of logits (row cached in smem) -> fp32 d_out
    logsoftmax_smem_kernel<<<rows, 256, LSM_SMEM>>>(logits, (float*)d_out, V);
}